// round 16
// baseline (speedup 1.0000x reference)
#include <cuda_runtime.h>
#include <cuda_bf16.h>
#include <cstdint>

#define B_  8
#define N_  8192
#define M_  2048
#define C1_ 128
#define C2_ 256
#define H_  256
#define KTOT (C1_ + C2_)

// ---------------- scratch (no allocation allowed) ----------------
__device__ int   g_idx[B_ * N_ * 3];
__device__ float g_w[B_ * N_ * 3];
__device__ __nv_bfloat16 g_w1h[H_ * KTOT];
__device__ __nv_bfloat16 g_w1l[H_ * KTOT];
__device__ __nv_bfloat16 g_w2h[H_ * H_];
__device__ __nv_bfloat16 g_w2l[H_ * H_];
__device__ __nv_bfloat16 g_x1h[(size_t)B_ * C2_ * N_];   // interp (b, k<256, n) bf16 hi
__device__ __nv_bfloat16 g_x1l[(size_t)B_ * C2_ * N_];
__device__ __nv_bfloat16 g_hh[(size_t)B_ * H_ * N_];     // hidden (b, m, n) bf16 hi
__device__ __nv_bfloat16 g_hl[(size_t)B_ * H_ * N_];

// ---------------- small helpers ----------------
__device__ __forceinline__ uint32_t smem_u32(const void* p) {
    uint32_t a;
    asm("{ .reg .u64 t; cvta.to.shared.u64 t, %1; cvt.u32.u64 %0, t; }" : "=r"(a) : "l"(p));
    return a;
}
__device__ __forceinline__ void cp16(uint32_t dst, const void* src) {
    asm volatile("cp.async.cg.shared.global [%0], [%1], 16;" :: "r"(dst), "l"(src));
}
#define CP_COMMIT() asm volatile("cp.async.commit_group;" ::: "memory")
#define CP_WAIT0()  asm volatile("cp.async.wait_group 0;" ::: "memory")

__device__ __forceinline__ void ldm_x4(uint32_t* r, uint32_t a) {
    asm volatile("ldmatrix.sync.aligned.m8n8.x4.shared.b16 {%0,%1,%2,%3}, [%4];"
                 : "=r"(r[0]), "=r"(r[1]), "=r"(r[2]), "=r"(r[3]) : "r"(a));
}
__device__ __forceinline__ void ldm_x4t(uint32_t* r, uint32_t a) {
    asm volatile("ldmatrix.sync.aligned.m8n8.x4.trans.shared.b16 {%0,%1,%2,%3}, [%4];"
                 : "=r"(r[0]), "=r"(r[1]), "=r"(r[2]), "=r"(r[3]) : "r"(a));
}
__device__ __forceinline__ void mma_bf16(float* c, const uint32_t* a, const uint32_t* b) {
    asm volatile(
        "mma.sync.aligned.m16n8k16.row.col.f32.bf16.bf16.f32 "
        "{%0,%1,%2,%3}, {%4,%5,%6,%7}, {%8,%9}, {%0,%1,%2,%3};"
        : "+f"(c[0]), "+f"(c[1]), "+f"(c[2]), "+f"(c[3])
        : "r"(a[0]), "r"(a[1]), "r"(a[2]), "r"(a[3]), "r"(b[0]), "r"(b[1]));
}
__device__ __forceinline__ void split_bf16(float v, __nv_bfloat16& hi, __nv_bfloat16& lo) {
    hi = __float2bfloat16_rn(v);
    lo = __float2bfloat16_rn(v - __bfloat162float(hi));
}
__device__ __forceinline__ uint32_t pack2(__nv_bfloat16 a, __nv_bfloat16 b) {
    __nv_bfloat162 p(a, b);
    return *(uint32_t*)&p;
}

// ---------------- 3-NN (expanded form) + folded W conversion ----------------
// W conversion (was wconv_kernel) folded in as a preamble: 256 blocks x 640 elems
// covers W1 (98304) + W2 (65536) exactly. Runs before smem coord staging; knn
// precedes both GEMMs so the W dependency is preserved. Saves a launch.
__global__ __launch_bounds__(256) void knn_kernel(const float* __restrict__ unknown,
                                                  const float* __restrict__ known,
                                                  const float* __restrict__ W1,
                                                  const float* __restrict__ W2) {
    __shared__ float4 kp[M_];                 // 32 KB
    const int b = blockIdx.y;
    const int bid = b * 32 + blockIdx.x;      // 0..255
    {
        const int e0 = bid * 640;
#pragma unroll
        for (int it = 0; it < 3; ++it) {
            const int e = e0 + it * 256 + threadIdx.x;
            if (e < e0 + 640) {
                if (e < H_ * KTOT) {
                    __nv_bfloat16 h, l;
                    split_bf16(W1[e], h, l);
                    g_w1h[e] = h; g_w1l[e] = l;
                } else {
                    const int e2 = e - H_ * KTOT;   // < 65536
                    __nv_bfloat16 h, l;
                    split_bf16(W2[e2], h, l);
                    g_w2h[e2] = h; g_w2l[e2] = l;
                }
            }
        }
    }

    const float* kb = known + (size_t)b * M_ * 3;
    for (int i = threadIdx.x; i < M_; i += 256) {
        const float x = kb[3 * i + 0];
        const float y = kb[3 * i + 1];
        const float z = kb[3 * i + 2];
        kp[i] = make_float4(-2.f * x, -2.f * y, -2.f * z,
                            fmaf(x, x, fmaf(y, y, z * z)));
    }
    __syncthreads();

    const int n = blockIdx.x * 256 + threadIdx.x;
    const float* u = unknown + ((size_t)b * N_ + n) * 3;
    const float ux = u[0], uy = u[1], uz = u[2];
    const float un2 = fmaf(ux, ux, fmaf(uy, uy, uz * uz));

    float d0 = 3.4e38f, d1 = 3.4e38f, d2 = 3.4e38f;
    int i0 = 0, i1 = 0, i2 = 0;
#pragma unroll 8
    for (int m = 0; m < M_; ++m) {
        const float4 k = kp[m];
        const float d = fmaf(k.x, ux, fmaf(k.y, uy, fmaf(k.z, uz, k.w)));
        if (d < d2) {
            if (d < d1) {
                if (d < d0) { d2 = d1; i2 = i1; d1 = d0; i1 = i0; d0 = d; i0 = m; }
                else        { d2 = d1; i2 = i1; d1 = d;  i1 = m; }
            } else          { d2 = d;  i2 = m; }
        }
    }
    const float s0 = sqrtf(fmaxf(d0 + un2, 0.f));
    const float s1 = sqrtf(fmaxf(d1 + un2, 0.f));
    const float s2 = sqrtf(fmaxf(d2 + un2, 0.f));
    const float r0 = 1.f / (s0 + 1e-8f);
    const float r1 = 1.f / (s1 + 1e-8f);
    const float r2 = 1.f / (s2 + 1e-8f);
    const float inv = 1.f / (r0 + r1 + r2);
    const size_t o = ((size_t)b * N_ + n) * 3;
    g_idx[o] = i0; g_idx[o + 1] = i1; g_idx[o + 2] = i2;
    g_w[o] = r0 * inv; g_w[o + 1] = r1 * inv; g_w[o + 2] = r2 * inv;
}

// --------- interpolation -> g_x1h/g_x1l (bf16 hi/lo, k-major), 4 ch/block ---------
#define CCH 4
__global__ __launch_bounds__(256) void interp_kernel(const float* __restrict__ kf) {
    __shared__ float s[CCH][M_];              // 32 KB
    const int b = blockIdx.y;
    const int c0 = blockIdx.x * CCH;
    const float* base = kf + ((size_t)b * C2_ + c0) * M_;
    for (int i = threadIdx.x; i < CCH * M_; i += 256)
        s[i >> 11][i & (M_ - 1)] = base[i];
    __syncthreads();

    for (int n = threadIdx.x; n < N_; n += 256) {
        const size_t o = ((size_t)b * N_ + n) * 3;
        const int i0 = g_idx[o], i1 = g_idx[o + 1], i2 = g_idx[o + 2];
        const float w0 = g_w[o], w1 = g_w[o + 1], w2 = g_w[o + 2];
        __nv_bfloat16* oh = g_x1h + ((size_t)b * C2_ + c0) * N_ + n;
        __nv_bfloat16* ol = g_x1l + ((size_t)b * C2_ + c0) * N_ + n;
#pragma unroll
        for (int c = 0; c < CCH; ++c) {
            const float v = fmaf(w0, s[c][i0], fmaf(w1, s[c][i1], w2 * s[c][i2]));
            __nv_bfloat16 h, l;
            split_bf16(v, h, l);
            oh[(size_t)c * N_] = h;
            ol[(size_t)c * N_] = l;
        }
    }
}

// ======== bf16x3 HMMA GEMM:  D(128x128) = W @ X, warp tile 64x32 (2 CTAs/SM) ========
// (R13-verified config — concurrency/overlap of two independent CTAs per SM beats
//  both bigger warp tiles (reg ceiling) and one big CTA (single barrier domain).)
// mode 0 (K=384): chunks k<256 read pre-converted bf16 hi/lo (interp output);
//   chunks k>=256 cp.async fp32 unknow_feats and split in-kernel (no extra pass).
// mode 1 (K=256): all chunks read g_hh/g_hl bf16 directly.
#define KC    32
#define ARS   80                      // A row stride bytes (32 bf16 + pad)
#define BRS   272                     // B row stride bytes (128 bf16 + 16 pad)
#define OFF_AH 0
#define OFF_AL 10240
#define OFF_BH 20480
#define OFF_BL 29184
#define OFF_BF 37888                  // fp32 staging: 32 rows x 512B (mode 0 tail chunks)
#define STG    54272
#define GSM    (2 * STG)              // 108544 B dynamic smem

__global__ __launch_bounds__(256)
void mma_gemm_kernel(const float* __restrict__ uf, const float* __restrict__ bias,
                     float* __restrict__ out, int K, int mode) {
    extern __shared__ char smem[];
    const uint32_t sbase = smem_u32(smem);
    const int tid = threadIdx.x;
    const int wid = tid >> 5;
    const int lane = tid & 31;
    const int b = blockIdx.z;
    const int m0 = blockIdx.y * 128;
    const int n0 = blockIdx.x * 128;

    const __nv_bfloat16* Wh = (mode == 0) ? g_w1h : g_w2h;
    const __nv_bfloat16* Wl = (mode == 0) ? g_w1l : g_w2l;
    const __nv_bfloat16* Xh = (mode == 0) ? (g_x1h + (size_t)b * C2_ * N_)
                                          : (g_hh + (size_t)b * H_ * N_);
    const __nv_bfloat16* Xl = (mode == 0) ? (g_x1l + (size_t)b * C2_ * N_)
                                          : (g_hl + (size_t)b * H_ * N_);
    const float* uf_b = uf ? (uf + (size_t)b * C1_ * N_) : nullptr;

    auto issue = [&](int k0c, int s) {
        const uint32_t dbase = sbase + s * STG;
        // A: 2 mats x 128 rows x 64B -> 1024 cp16
#pragma unroll
        for (int i = 0; i < 4; ++i) {
            const int idx = tid + i * 256;
            const int mat = idx >> 9;
            const int r = (idx >> 2) & 127;
            const int c = idx & 3;
            const uint32_t dst = dbase + (mat ? OFF_AL : OFF_AH) + r * ARS + c * 16;
            const __nv_bfloat16* src = (mat ? Wl : Wh) + (size_t)(m0 + r) * K + k0c + c * 8;
            cp16(dst, src);
        }
        if (mode == 0 && k0c >= C2_) {
            // B fp32 tail: 32 k-rows x 512B -> 1024 cp16 (split in-kernel later)
#pragma unroll
            for (int i = 0; i < 4; ++i) {
                const int idx = tid + i * 256;
                const int r = idx >> 5;
                const int c = idx & 31;
                cp16(dbase + OFF_BF + r * 512 + c * 16,
                     uf_b + (size_t)(k0c - C2_ + r) * N_ + n0 + c * 4);
            }
        } else {
            // B bf16 hi/lo direct: 2 mats x 32 k-rows x 256B -> 1024 cp16
#pragma unroll
            for (int i = 0; i < 4; ++i) {
                const int idx = tid + i * 256;
                const int mat = idx >> 9;
                const int r = (idx >> 4) & 31;
                const int c = idx & 15;
                const uint32_t dst = dbase + (mat ? OFF_BL : OFF_BH) + r * BRS + c * 16;
                const __nv_bfloat16* src = (mat ? Xl : Xh) + (size_t)(k0c + r) * N_ + n0 + c * 8;
                cp16(dst, src);
            }
        }
    };

    const int wm = wid >> 2;            // 0..1  -> m offset (64)
    const int wn = wid & 3;             // 0..3  -> n offset (32)
    const int m_off = wm * 64;
    const int n_off = wn * 32;

    float acc[4][4][4];
#pragma unroll
    for (int i = 0; i < 4; ++i)
#pragma unroll
        for (int j = 0; j < 4; ++j)
#pragma unroll
            for (int q = 0; q < 4; ++q) acc[i][j][q] = 0.f;

    const int T = K / KC;
    issue(0, 0);
    CP_COMMIT();
    int buf = 0;

    for (int t = 0; t < T; ++t) {
        CP_WAIT0();
        __syncthreads();   // chunk t data ready; also: all warps done with buf^1's old data
        if (t + 1 < T) { issue((t + 1) * KC, buf ^ 1); CP_COMMIT(); }

        const uint32_t dbase = sbase + buf * STG;
        if (mode == 0 && t * KC >= C2_) {
            // split fp32 staging -> bf16 hi/lo (layout-preserving, k-major)
            const int r = tid >> 3;
            const int c0 = (tid & 7) * 16;
            const float* sf = (const float*)(smem + (size_t)buf * STG + OFF_BF + r * 512) + c0;
            union { uint4 v[2]; __nv_bfloat16 h[16]; } Hh, Ll;
#pragma unroll
            for (int i = 0; i < 16; ++i) {
                __nv_bfloat16 h, l;
                split_bf16(sf[i], h, l);
                Hh.h[i] = h; Ll.h[i] = l;
            }
            char* bh = smem + (size_t)buf * STG + OFF_BH + r * BRS + c0 * 2;
            char* bl = smem + (size_t)buf * STG + OFF_BL + r * BRS + c0 * 2;
            *(uint4*)bh = Hh.v[0]; *(uint4*)(bh + 16) = Hh.v[1];
            *(uint4*)bl = Ll.v[0]; *(uint4*)(bl + 16) = Ll.v[1];
            __syncthreads();
        }

        const uint32_t ah_b = dbase + OFF_AH;
        const uint32_t al_b = dbase + OFF_AL;
        const uint32_t bh_b = dbase + OFF_BH;
        const uint32_t bl_b = dbase + OFF_BL;

#pragma unroll
        for (int k16 = 0; k16 < 2; ++k16) {
            uint32_t Ah[4][4], Al[4][4], Bh[4][2], Bl[4][2];
            // B fragments: x4.trans loads 2 n-subtiles (16 n) per instruction.
            const uint32_t boff = (uint32_t)(k16 * 16 + (lane & 15)) * BRS
                                + (n_off + (lane >> 4) * 8) * 2;
            ldm_x4t(&Bh[0][0], bh_b + boff);
            ldm_x4t(&Bh[2][0], bh_b + boff + 32);
            ldm_x4t(&Bl[0][0], bl_b + boff);
            ldm_x4t(&Bl[2][0], bl_b + boff + 32);
            // A fragments (m-major)
            const uint32_t aoff = (uint32_t)(m_off + (lane & 15)) * ARS
                                + (lane >> 4) * 16 + k16 * 32;
#pragma unroll
            for (int mt = 0; mt < 4; ++mt) {
                ldm_x4(Ah[mt], ah_b + aoff + mt * 16 * ARS);
                ldm_x4(Al[mt], al_b + aoff + mt * 16 * ARS);
            }
            // 3 combos (Ah*Bh + Ah*Bl + Al*Bh)
#pragma unroll
            for (int mt = 0; mt < 4; ++mt)
#pragma unroll
                for (int nt = 0; nt < 4; ++nt) mma_bf16(acc[mt][nt], Ah[mt], Bh[nt]);
#pragma unroll
            for (int mt = 0; mt < 4; ++mt)
#pragma unroll
                for (int nt = 0; nt < 4; ++nt) mma_bf16(acc[mt][nt], Ah[mt], Bl[nt]);
#pragma unroll
            for (int mt = 0; mt < 4; ++mt)
#pragma unroll
                for (int nt = 0; nt < 4; ++nt) mma_bf16(acc[mt][nt], Al[mt], Bh[nt]);
        }
        buf ^= 1;   // no trailing sync: next iter's leading sync orders buffer reuse
    }

    // ---------------- epilogue ----------------
    if (mode == 1) {
        // final layer: out[b][m][n] = relu(acc + bias), fp32
#pragma unroll
        for (int mt = 0; mt < 4; ++mt) {
            const int r0 = m0 + m_off + mt * 16 + (lane >> 2);
            const float bi0 = bias[r0];
            const float bi1 = bias[r0 + 8];
#pragma unroll
            for (int nt = 0; nt < 4; ++nt) {
                const int cc = n0 + n_off + nt * 8 + (lane & 3) * 2;
                float2 v0, v1;
                v0.x = fmaxf(acc[mt][nt][0] + bi0, 0.f);
                v0.y = fmaxf(acc[mt][nt][1] + bi0, 0.f);
                v1.x = fmaxf(acc[mt][nt][2] + bi1, 0.f);
                v1.y = fmaxf(acc[mt][nt][3] + bi1, 0.f);
                *(float2*)(out + ((size_t)b * H_ + r0) * N_ + cc) = v0;
                *(float2*)(out + ((size_t)b * H_ + r0 + 8) * N_ + cc) = v1;
            }
        }
    } else {
        // hidden layer: relu(acc + bias) -> g_hh/g_hl (b, m, n) bf16 hi/lo
#pragma unroll
        for (int mt = 0; mt < 4; ++mt) {
            const int r0 = m0 + m_off + mt * 16 + (lane >> 2);
            const float bi0 = bias[r0];
            const float bi1 = bias[r0 + 8];
#pragma unroll
            for (int nt = 0; nt < 4; ++nt) {
                const int cc = n0 + n_off + nt * 8 + (lane & 3) * 2;
                const float v0 = fmaxf(acc[mt][nt][0] + bi0, 0.f);
                const float v1 = fmaxf(acc[mt][nt][1] + bi0, 0.f);
                const float v2 = fmaxf(acc[mt][nt][2] + bi1, 0.f);
                const float v3 = fmaxf(acc[mt][nt][3] + bi1, 0.f);
                __nv_bfloat16 h0, l0, h1, l1, h2, l2, h3, l3;
                split_bf16(v0, h0, l0); split_bf16(v1, h1, l1);
                split_bf16(v2, h2, l2); split_bf16(v3, h3, l3);
                const size_t j0 = ((size_t)b * H_ + r0) * N_ + cc;
                const size_t j1 = ((size_t)b * H_ + r0 + 8) * N_ + cc;
                *(uint32_t*)(g_hh + j0) = pack2(h0, h1);
                *(uint32_t*)(g_hl + j0) = pack2(l0, l1);
                *(uint32_t*)(g_hh + j1) = pack2(h2, h3);
                *(uint32_t*)(g_hl + j1) = pack2(l2, l3);
            }
        }
    }
}

// ---------------- launch ----------------
extern "C" void kernel_launch(void* const* d_in, const int* in_sizes, int n_in,
                              void* d_out, int out_size) {
    const float* unknown      = (const float*)d_in[0];  // (B, N, 3)
    const float* known        = (const float*)d_in[1];  // (B, M, 3)
    const float* unknow_feats = (const float*)d_in[2];  // (B, C1, N)
    const float* known_feats  = (const float*)d_in[3];  // (B, C2, M)
    const float* W1           = (const float*)d_in[4];  // (H, C1+C2)
    const float* b1           = (const float*)d_in[5];  // (H)
    const float* W2           = (const float*)d_in[6];  // (H, H)
    const float* b2           = (const float*)d_in[7];  // (H)
    float* out = (float*)d_out;                         // (B, H, N)

    cudaFuncSetAttribute(mma_gemm_kernel, cudaFuncAttributeMaxDynamicSharedMemorySize, GSM);

    knn_kernel<<<dim3(N_ / 256, B_), 256>>>(unknown, known, W1, W2);
    interp_kernel<<<dim3(C2_ / CCH, B_), 256>>>(known_feats);

    // layer 1: hidden = relu(W1 @ [interp; unknow] + b1) -> g_hh/g_hl (bf16 hi/lo)
    mma_gemm_kernel<<<dim3(N_ / 128, 2, B_), 256, GSM>>>(unknow_feats, b1, nullptr, KTOT, 0);
    // layer 2: out = relu(W2 @ hidden + b2), fp32
    mma_gemm_kernel<<<dim3(N_ / 128, 2, B_), 256, GSM>>>(nullptr, b2, out, H_, 1);
}

// round 17
// speedup vs baseline: 1.5350x; 1.5350x over previous
#include <cuda_runtime.h>
#include <cuda_bf16.h>
#include <cstdint>

#define B_  8
#define N_  8192
#define M_  2048
#define C1_ 128
#define C2_ 256
#define H_  256
#define KTOT (C1_ + C2_)

// ---------------- scratch (no allocation allowed) ----------------
__device__ int   g_idx[B_ * N_ * 3];
__device__ float g_w[B_ * N_ * 3];
__device__ __nv_bfloat16 g_w1h[H_ * KTOT];
__device__ __nv_bfloat16 g_w1l[H_ * KTOT];
__device__ __nv_bfloat16 g_w2h[H_ * H_];
__device__ __nv_bfloat16 g_w2l[H_ * H_];
__device__ __nv_bfloat16 g_x1h[(size_t)B_ * C2_ * N_];   // interp (b, k<256, n) bf16 hi
__device__ __nv_bfloat16 g_x1l[(size_t)B_ * C2_ * N_];
__device__ __nv_bfloat16 g_hh[(size_t)B_ * H_ * N_];     // hidden (b, m, n) bf16 hi
__device__ __nv_bfloat16 g_hl[(size_t)B_ * H_ * N_];

// ---------------- small helpers ----------------
__device__ __forceinline__ uint32_t smem_u32(const void* p) {
    uint32_t a;
    asm("{ .reg .u64 t; cvta.to.shared.u64 t, %1; cvt.u32.u64 %0, t; }" : "=r"(a) : "l"(p));
    return a;
}
__device__ __forceinline__ void cp16(uint32_t dst, const void* src) {
    asm volatile("cp.async.cg.shared.global [%0], [%1], 16;" :: "r"(dst), "l"(src));
}
#define CP_COMMIT() asm volatile("cp.async.commit_group;" ::: "memory")
#define CP_WAIT0()  asm volatile("cp.async.wait_group 0;" ::: "memory")

__device__ __forceinline__ void ldm_x4(uint32_t* r, uint32_t a) {
    asm volatile("ldmatrix.sync.aligned.m8n8.x4.shared.b16 {%0,%1,%2,%3}, [%4];"
                 : "=r"(r[0]), "=r"(r[1]), "=r"(r[2]), "=r"(r[3]) : "r"(a));
}
__device__ __forceinline__ void ldm_x4t(uint32_t* r, uint32_t a) {
    asm volatile("ldmatrix.sync.aligned.m8n8.x4.trans.shared.b16 {%0,%1,%2,%3}, [%4];"
                 : "=r"(r[0]), "=r"(r[1]), "=r"(r[2]), "=r"(r[3]) : "r"(a));
}
__device__ __forceinline__ void mma_bf16(float* c, const uint32_t* a, const uint32_t* b) {
    asm volatile(
        "mma.sync.aligned.m16n8k16.row.col.f32.bf16.bf16.f32 "
        "{%0,%1,%2,%3}, {%4,%5,%6,%7}, {%8,%9}, {%0,%1,%2,%3};"
        : "+f"(c[0]), "+f"(c[1]), "+f"(c[2]), "+f"(c[3])
        : "r"(a[0]), "r"(a[1]), "r"(a[2]), "r"(a[3]), "r"(b[0]), "r"(b[1]));
}
__device__ __forceinline__ void split_bf16(float v, __nv_bfloat16& hi, __nv_bfloat16& lo) {
    hi = __float2bfloat16_rn(v);
    lo = __float2bfloat16_rn(v - __bfloat162float(hi));
}
__device__ __forceinline__ uint32_t pack2(__nv_bfloat16 a, __nv_bfloat16 b) {
    __nv_bfloat162 p(a, b);
    return *(uint32_t*)&p;
}

// ---------------- 3-NN: expanded form, 3 FFMA per pair ----------------
// smem point = (-2kx, -2ky, -2kz, |k|^2); score d' = |k|^2 - 2u.k  (d = d' + |u|^2)
__global__ __launch_bounds__(256) void knn_kernel(const float* __restrict__ unknown,
                                                  const float* __restrict__ known) {
    __shared__ float4 kp[M_];                 // 32 KB
    const int b = blockIdx.y;
    const float* kb = known + (size_t)b * M_ * 3;
    for (int i = threadIdx.x; i < M_; i += 256) {
        const float x = kb[3 * i + 0];
        const float y = kb[3 * i + 1];
        const float z = kb[3 * i + 2];
        kp[i] = make_float4(-2.f * x, -2.f * y, -2.f * z,
                            fmaf(x, x, fmaf(y, y, z * z)));
    }
    __syncthreads();

    const int n = blockIdx.x * 256 + threadIdx.x;
    const float* u = unknown + ((size_t)b * N_ + n) * 3;
    const float ux = u[0], uy = u[1], uz = u[2];
    const float un2 = fmaf(ux, ux, fmaf(uy, uy, uz * uz));

    float d0 = 3.4e38f, d1 = 3.4e38f, d2 = 3.4e38f;
    int i0 = 0, i1 = 0, i2 = 0;
#pragma unroll 8
    for (int m = 0; m < M_; ++m) {
        const float4 k = kp[m];
        const float d = fmaf(k.x, ux, fmaf(k.y, uy, fmaf(k.z, uz, k.w)));
        if (d < d2) {
            if (d < d1) {
                if (d < d0) { d2 = d1; i2 = i1; d1 = d0; i1 = i0; d0 = d; i0 = m; }
                else        { d2 = d1; i2 = i1; d1 = d;  i1 = m; }
            } else          { d2 = d;  i2 = m; }
        }
    }
    const float s0 = sqrtf(fmaxf(d0 + un2, 0.f));
    const float s1 = sqrtf(fmaxf(d1 + un2, 0.f));
    const float s2 = sqrtf(fmaxf(d2 + un2, 0.f));
    const float r0 = 1.f / (s0 + 1e-8f);
    const float r1 = 1.f / (s1 + 1e-8f);
    const float r2 = 1.f / (s2 + 1e-8f);
    const float inv = 1.f / (r0 + r1 + r2);
    const size_t o = ((size_t)b * N_ + n) * 3;
    g_idx[o] = i0; g_idx[o + 1] = i1; g_idx[o + 2] = i2;
    g_w[o] = r0 * inv; g_w[o + 1] = r1 * inv; g_w[o + 2] = r2 * inv;
}

// --------- interpolation -> g_x1h/g_x1l (bf16 hi/lo, k-major), 4 ch/block ---------
#define CCH 4
__global__ __launch_bounds__(256) void interp_kernel(const float* __restrict__ kf) {
    __shared__ float s[CCH][M_];              // 32 KB
    const int b = blockIdx.y;
    const int c0 = blockIdx.x * CCH;
    const float* base = kf + ((size_t)b * C2_ + c0) * M_;
    for (int i = threadIdx.x; i < CCH * M_; i += 256)
        s[i >> 11][i & (M_ - 1)] = base[i];
    __syncthreads();

    for (int n = threadIdx.x; n < N_; n += 256) {
        const size_t o = ((size_t)b * N_ + n) * 3;
        const int i0 = g_idx[o], i1 = g_idx[o + 1], i2 = g_idx[o + 2];
        const float w0 = g_w[o], w1 = g_w[o + 1], w2 = g_w[o + 2];
        __nv_bfloat16* oh = g_x1h + ((size_t)b * C2_ + c0) * N_ + n;
        __nv_bfloat16* ol = g_x1l + ((size_t)b * C2_ + c0) * N_ + n;
#pragma unroll
        for (int c = 0; c < CCH; ++c) {
            const float v = fmaf(w0, s[c][i0], fmaf(w1, s[c][i1], w2 * s[c][i2]));
            __nv_bfloat16 h, l;
            split_bf16(v, h, l);
            oh[(size_t)c * N_] = h;
            ol[(size_t)c * N_] = l;
        }
    }
}

// ---------------- W -> bf16 hi/lo ----------------
__global__ __launch_bounds__(256) void wconv_kernel(const float* __restrict__ W1,
                                                    const float* __restrict__ W2) {
    const int i = blockIdx.x * 256 + threadIdx.x;
    if (i < H_ * KTOT) { __nv_bfloat16 h, l; split_bf16(W1[i], h, l); g_w1h[i] = h; g_w1l[i] = l; }
    if (i < H_ * H_)   { __nv_bfloat16 h, l; split_bf16(W2[i], h, l); g_w2h[i] = h; g_w2l[i] = l; }
}

// ======== bf16x3 HMMA GEMM:  D(128x128) = W @ X, warp tile 64x32 (2 CTAs/SM) ========
// mode 0 (K=384): chunks k<256 read pre-converted bf16 hi/lo (interp output);
//   chunks k>=256 cp.async fp32 unknow_feats and split in-kernel (no extra pass).
// mode 1 (K=256): all chunks read g_hh/g_hl bf16 directly.
// Device-global operands selected in-kernel by mode (never host-side args).
#define KC    32
#define ARS   80                      // A row stride bytes (32 bf16 + pad)
#define BRS   272                     // B row stride bytes (128 bf16 + 16 pad)
#define OFF_AH 0
#define OFF_AL 10240
#define OFF_BH 20480
#define OFF_BL 29184
#define OFF_BF 37888                  // fp32 staging: 32 rows x 512B (mode 0 tail chunks)
#define STG    54272
#define GSM    (2 * STG)              // 108544 B dynamic smem

__global__ __launch_bounds__(256)
void mma_gemm_kernel(const float* __restrict__ uf, const float* __restrict__ bias,
                     float* __restrict__ out, int K, int mode) {
    extern __shared__ char smem[];
    const uint32_t sbase = smem_u32(smem);
    const int tid = threadIdx.x;
    const int wid = tid >> 5;
    const int lane = tid & 31;
    const int b = blockIdx.z;
    const int m0 = blockIdx.y * 128;
    const int n0 = blockIdx.x * 128;

    const __nv_bfloat16* Wh = (mode == 0) ? g_w1h : g_w2h;
    const __nv_bfloat16* Wl = (mode == 0) ? g_w1l : g_w2l;
    const __nv_bfloat16* Xh = (mode == 0) ? (g_x1h + (size_t)b * C2_ * N_)
                                          : (g_hh + (size_t)b * H_ * N_);
    const __nv_bfloat16* Xl = (mode == 0) ? (g_x1l + (size_t)b * C2_ * N_)
                                          : (g_hl + (size_t)b * H_ * N_);
    const float* uf_b = uf ? (uf + (size_t)b * C1_ * N_) : nullptr;

    auto issue = [&](int k0c, int s) {
        const uint32_t dbase = sbase + s * STG;
        // A: 2 mats x 128 rows x 64B -> 1024 cp16
#pragma unroll
        for (int i = 0; i < 4; ++i) {
            const int idx = tid + i * 256;
            const int mat = idx >> 9;
            const int r = (idx >> 2) & 127;
            const int c = idx & 3;
            const uint32_t dst = dbase + (mat ? OFF_AL : OFF_AH) + r * ARS + c * 16;
            const __nv_bfloat16* src = (mat ? Wl : Wh) + (size_t)(m0 + r) * K + k0c + c * 8;
            cp16(dst, src);
        }
        if (mode == 0 && k0c >= C2_) {
            // B fp32 tail: 32 k-rows x 512B -> 1024 cp16 (split in-kernel later)
#pragma unroll
            for (int i = 0; i < 4; ++i) {
                const int idx = tid + i * 256;
                const int r = idx >> 5;
                const int c = idx & 31;
                cp16(dbase + OFF_BF + r * 512 + c * 16,
                     uf_b + (size_t)(k0c - C2_ + r) * N_ + n0 + c * 4);
            }
        } else {
            // B bf16 hi/lo direct: 2 mats x 32 k-rows x 256B -> 1024 cp16
#pragma unroll
            for (int i = 0; i < 4; ++i) {
                const int idx = tid + i * 256;
                const int mat = idx >> 9;
                const int r = (idx >> 4) & 31;
                const int c = idx & 15;
                const uint32_t dst = dbase + (mat ? OFF_BL : OFF_BH) + r * BRS + c * 16;
                const __nv_bfloat16* src = (mat ? Xl : Xh) + (size_t)(k0c + r) * N_ + n0 + c * 8;
                cp16(dst, src);
            }
        }
    };

    const int wm = wid >> 2;            // 0..1  -> m offset (64)
    const int wn = wid & 3;             // 0..3  -> n offset (32)
    const int m_off = wm * 64;
    const int n_off = wn * 32;

    float acc[4][4][4];
#pragma unroll
    for (int i = 0; i < 4; ++i)
#pragma unroll
        for (int j = 0; j < 4; ++j)
#pragma unroll
            for (int q = 0; q < 4; ++q) acc[i][j][q] = 0.f;

    const int T = K / KC;
    issue(0, 0);
    CP_COMMIT();
    int buf = 0;

    for (int t = 0; t < T; ++t) {
        CP_WAIT0();
        __syncthreads();   // chunk t data ready; also: all warps done with buf^1's old data
        if (t + 1 < T) { issue((t + 1) * KC, buf ^ 1); CP_COMMIT(); }

        const uint32_t dbase = sbase + buf * STG;
        if (mode == 0 && t * KC >= C2_) {
            // split fp32 staging -> bf16 hi/lo (layout-preserving, k-major)
            const int r = tid >> 3;
            const int c0 = (tid & 7) * 16;
            const float* sf = (const float*)(smem + (size_t)buf * STG + OFF_BF + r * 512) + c0;
            union { uint4 v[2]; __nv_bfloat16 h[16]; } Hh, Ll;
#pragma unroll
            for (int i = 0; i < 16; ++i) {
                __nv_bfloat16 h, l;
                split_bf16(sf[i], h, l);
                Hh.h[i] = h; Ll.h[i] = l;
            }
            char* bh = smem + (size_t)buf * STG + OFF_BH + r * BRS + c0 * 2;
            char* bl = smem + (size_t)buf * STG + OFF_BL + r * BRS + c0 * 2;
            *(uint4*)bh = Hh.v[0]; *(uint4*)(bh + 16) = Hh.v[1];
            *(uint4*)bl = Ll.v[0]; *(uint4*)(bl + 16) = Ll.v[1];
            __syncthreads();
        }

        const uint32_t ah_b = dbase + OFF_AH;
        const uint32_t al_b = dbase + OFF_AL;
        const uint32_t bh_b = dbase + OFF_BH;
        const uint32_t bl_b = dbase + OFF_BL;

#pragma unroll
        for (int k16 = 0; k16 < 2; ++k16) {
            uint32_t Ah[4][4], Al[4][4], Bh[4][2], Bl[4][2];
            // B fragments: x4.trans loads 2 n-subtiles (16 n) per instruction.
            const uint32_t boff = (uint32_t)(k16 * 16 + (lane & 15)) * BRS
                                + (n_off + (lane >> 4) * 8) * 2;
            ldm_x4t(&Bh[0][0], bh_b + boff);
            ldm_x4t(&Bh[2][0], bh_b + boff + 32);
            ldm_x4t(&Bl[0][0], bl_b + boff);
            ldm_x4t(&Bl[2][0], bl_b + boff + 32);
            // A fragments (m-major)
            const uint32_t aoff = (uint32_t)(m_off + (lane & 15)) * ARS
                                + (lane >> 4) * 16 + k16 * 32;
#pragma unroll
            for (int mt = 0; mt < 4; ++mt) {
                ldm_x4(Ah[mt], ah_b + aoff + mt * 16 * ARS);
                ldm_x4(Al[mt], al_b + aoff + mt * 16 * ARS);
            }
            // 3 combos (Ah*Bh + Ah*Bl + Al*Bh)
#pragma unroll
            for (int mt = 0; mt < 4; ++mt)
#pragma unroll
                for (int nt = 0; nt < 4; ++nt) mma_bf16(acc[mt][nt], Ah[mt], Bh[nt]);
#pragma unroll
            for (int mt = 0; mt < 4; ++mt)
#pragma unroll
                for (int nt = 0; nt < 4; ++nt) mma_bf16(acc[mt][nt], Ah[mt], Bl[nt]);
#pragma unroll
            for (int mt = 0; mt < 4; ++mt)
#pragma unroll
                for (int nt = 0; nt < 4; ++nt) mma_bf16(acc[mt][nt], Al[mt], Bh[nt]);
        }
        buf ^= 1;   // no trailing sync: next iter's leading sync orders buffer reuse
    }

    // ---------------- epilogue ----------------
    if (mode == 1) {
        // final layer: out[b][m][n] = relu(acc + bias), fp32
#pragma unroll
        for (int mt = 0; mt < 4; ++mt) {
            const int r0 = m0 + m_off + mt * 16 + (lane >> 2);
            const float bi0 = bias[r0];
            const float bi1 = bias[r0 + 8];
#pragma unroll
            for (int nt = 0; nt < 4; ++nt) {
                const int cc = n0 + n_off + nt * 8 + (lane & 3) * 2;
                float2 v0, v1;
                v0.x = fmaxf(acc[mt][nt][0] + bi0, 0.f);
                v0.y = fmaxf(acc[mt][nt][1] + bi0, 0.f);
                v1.x = fmaxf(acc[mt][nt][2] + bi1, 0.f);
                v1.y = fmaxf(acc[mt][nt][3] + bi1, 0.f);
                *(float2*)(out + ((size_t)b * H_ + r0) * N_ + cc) = v0;
                *(float2*)(out + ((size_t)b * H_ + r0 + 8) * N_ + cc) = v1;
            }
        }
    } else {
        // hidden layer: relu(acc + bias) -> g_hh/g_hl (b, m, n) bf16 hi/lo
#pragma unroll
        for (int mt = 0; mt < 4; ++mt) {
            const int r0 = m0 + m_off + mt * 16 + (lane >> 2);
            const float bi0 = bias[r0];
            const float bi1 = bias[r0 + 8];
#pragma unroll
            for (int nt = 0; nt < 4; ++nt) {
                const int cc = n0 + n_off + nt * 8 + (lane & 3) * 2;
                const float v0 = fmaxf(acc[mt][nt][0] + bi0, 0.f);
                const float v1 = fmaxf(acc[mt][nt][1] + bi0, 0.f);
                const float v2 = fmaxf(acc[mt][nt][2] + bi1, 0.f);
                const float v3 = fmaxf(acc[mt][nt][3] + bi1, 0.f);
                __nv_bfloat16 h0, l0, h1, l1, h2, l2, h3, l3;
                split_bf16(v0, h0, l0); split_bf16(v1, h1, l1);
                split_bf16(v2, h2, l2); split_bf16(v3, h3, l3);
                const size_t j0 = ((size_t)b * H_ + r0) * N_ + cc;
                const size_t j1 = ((size_t)b * H_ + r0 + 8) * N_ + cc;
                *(uint32_t*)(g_hh + j0) = pack2(h0, h1);
                *(uint32_t*)(g_hl + j0) = pack2(l0, l1);
                *(uint32_t*)(g_hh + j1) = pack2(h2, h3);
                *(uint32_t*)(g_hl + j1) = pack2(l2, l3);
            }
        }
    }
}

// ---------------- launch ----------------
extern "C" void kernel_launch(void* const* d_in, const int* in_sizes, int n_in,
                              void* d_out, int out_size) {
    const float* unknown      = (const float*)d_in[0];  // (B, N, 3)
    const float* known        = (const float*)d_in[1];  // (B, M, 3)
    const float* unknow_feats = (const float*)d_in[2];  // (B, C1, N)
    const float* known_feats  = (const float*)d_in[3];  // (B, C2, M)
    const float* W1           = (const float*)d_in[4];  // (H, C1+C2)
    const float* b1           = (const float*)d_in[5];  // (H)
    const float* W2           = (const float*)d_in[6];  // (H, H)
    const float* b2           = (const float*)d_in[7];  // (H)
    float* out = (float*)d_out;                         // (B, H, N)

    cudaFuncSetAttribute(mma_gemm_kernel, cudaFuncAttributeMaxDynamicSharedMemorySize, GSM);

    knn_kernel<<<dim3(N_ / 256, B_), 256>>>(unknown, known);
    interp_kernel<<<dim3(C2_ / CCH, B_), 256>>>(known_feats);
    wconv_kernel<<<(H_ * KTOT + 255) / 256, 256>>>(W1, W2);

    // layer 1: hidden = relu(W1 @ [interp; unknow] + b1) -> g_hh/g_hl (bf16 hi/lo)
    mma_gemm_kernel<<<dim3(N_ / 128, 2, B_), 256, GSM>>>(unknow_feats, b1, nullptr, KTOT, 0);
    // layer 2: out = relu(W2 @ hidden + b2), fp32
    mma_gemm_kernel<<<dim3(N_ / 128, 2, B_), 256, GSM>>>(nullptr, b2, out, H_, 1);
}